// round 11
// baseline (speedup 1.0000x reference)
#include <cuda_runtime.h>
#include <stdint.h>

#define HH 224
#define WW 224
#define STEPS 32
#define NIMG 24            // 8 * 3
#define NSTRIPS 45
#define RPS 5              // site rows per strip: 45*5 = 225 exactly
#define NROWS (RPS + 1)    // pixel rows touched (incl. top halo)
#define NPLANES 3          // per-strip counts <= 5 -> 3 bit-planes

// Per-image/threshold ECC accumulators + completion counter.
// Zero-initialized at load; the last block resets them each launch, so the
// "all zero at entry" invariant holds across graph replays.
__device__ int g_ecc[NIMG * STEPS];
__device__ unsigned int g_done;

// Exact cumulative indicator mask: bit j set iff v <= t_j, where
// t_j = fl(-2 + fl(j * fl(4/31))) (bit-identical to jnp.linspace(-2,2,32) f32).
// g = (v+2)*7.75 + 1/64 bias: floor(clamp(g)) is k* or k*-1; one compare
// v > t_k fixes it exactly. k==32 (v > t_31, incl. +inf) -> 64-bit shift -> 0.
// floorf keeps k in float (no I2F on the t path); F2I only for the shift.
__device__ __forceinline__ unsigned int mask_of(float v) {
    float g = __fmaf_rn(v, 7.75f, 15.515625f);
    g = floorf(fminf(fmaxf(g, 0.0f), 31.0f));
    float t = __fadd_rn(-2.0f, __fmul_rn(g, 4.0f / 31.0f));
    int k = (int)g + ((v > t) ? 1 : 0);
    return (unsigned int)(0xFFFFFFFFull << k);
}

__global__ __launch_bounds__(256, 6)   // 40-reg budget: room to batch loads
void ecc_fused_kernel(const float* __restrict__ x, float* __restrict__ out) {
    const int lane  = threadIdx.x;          // 0..31
    const int w     = threadIdx.y;          // 0..7
    const int strip = blockIdx.x;           // 0..NSTRIPS-1
    const int img   = blockIdx.y;           // 0..23

    // Lane L of warp w owns pixel column pc = 31*w + L - 1 (lane 0 = halo dup).
    // Site column for lane L>=1 is pc; cols 0..224 covered exactly once.
    const int pc    = 31 * w + lane - 1;
    const bool colv = (unsigned)pc < (unsigned)WW;
    const float INF = __int_as_float(0x7f800000);

    const int r0 = strip * RPS;             // site rows [r0, r0+RPS)
    const float* __restrict__ q = x + img * (HH * WW) + (colv ? pc : 0);

    // ---- batched loads: fast path (interior strips) uses immediate offsets ----
    float vrow[NROWS];
    if (strip >= 1 && strip <= NSTRIPS - 2) {       // uniform branch per block
        const float* __restrict__ r = q + (r0 - 1) * WW;
        #pragma unroll
        for (int t = 0; t < NROWS; ++t) {
            const float v = __ldg(r + t * WW);      // LDG with immediate offset
            vrow[t] = colv ? v : INF;
        }
    } else {
        #pragma unroll
        for (int t = 0; t < NROWS; ++t) {
            const int pr  = r0 - 1 + t;                     // may be OOB
            const int prc = min(max(pr, 0), HH - 1);
            const float v = __ldg(q + prc * WW);
            const bool ok = colv && ((unsigned)pr < (unsigned)HH);
            vrow[t] = ok ? v : INF;
        }
    }

    // ---- batched masks, then batched shfls ----
    unsigned m[NROWS];
    #pragma unroll
    for (int t = 0; t < NROWS; ++t) m[t] = mask_of(vrow[t]);
    unsigned sm[NROWS];
    #pragma unroll
    for (int t = 0; t < NROWS; ++t) {
        unsigned y = __shfl_up_sync(0xFFFFFFFFu, m[t], 1);
        sm[t] = (lane == 0) ? 0u : y;
    }

    // ---- pure-ALU body: 5 site rows, no rolling dependence ----
    unsigned P[NPLANES], M[NPLANES];
    #pragma unroll
    for (int k = 0; k < NPLANES; ++k) { P[k] = 0u; M[k] = 0u; }

    #pragma unroll
    for (int r = 0; r < RPS; ++r) {
        const unsigned pmc = sm[r],     pmd = m[r];      // row i-1: left, own
        const unsigned mc  = sm[r + 1], md  = m[r + 1];  // row i  : left, own
        const unsigned u     = pmd | mc | md;
        const unsigned plus  = pmc & ~u;                 // vertex net +1
        const unsigned minus = pmd & mc & ~md;           // edge-pair net -1

        unsigned cp = plus, cm = minus, tp, tm;
        #pragma unroll
        for (int k = 0; k < NPLANES; ++k) {
            tp = P[k] & cp;  tm = M[k] & cm;
            P[k] ^= cp;      M[k] ^= cm;
            cp = tp;         cm = tm;
        }
    }

    // ---- per-warp 32x32 bit transpose (3 instr/stage) + weighted popc ----
    unsigned keepm[5]; int amt[5];
    {
        const unsigned Ms[5] = {0xFFFF0000u, 0xFF00FF00u, 0xF0F0F0F0u,
                                0xCCCCCCCCu, 0xAAAAAAAAu};
        const int ds[5] = {16, 8, 4, 2, 1};
        #pragma unroll
        for (int s = 0; s < 5; ++s) {
            const bool b = (lane & ds[s]) != 0;
            keepm[s] = b ? Ms[s] : ~Ms[s];
            amt[s]   = b ? ds[s] : 32 - ds[s];
        }
    }
    int acc = 0;
    #pragma unroll
    for (int k = 0; k < 2 * NPLANES; ++k) {
        unsigned v = (k < NPLANES) ? P[k] : M[k - NPLANES];
        const int ds[5] = {16, 8, 4, 2, 1};
        #pragma unroll
        for (int s = 0; s < 5; ++s) {
            unsigned y = __shfl_xor_sync(0xFFFFFFFFu, v, ds[s]);
            unsigned r = __funnelshift_r(y, y, amt[s]);   // rotate covers both arms
            v = (v & keepm[s]) | (r & ~keepm[s]);         // 1 LOP3
        }
        const int wgt = __popc(v) << (k < NPLANES ? k : k - NPLANES);
        acc += (k < NPLANES) ? wgt : -wgt;
    }
    // lane j now holds this warp's net count for threshold j.

    // ---- single barrier; warp 0 owns the whole tail ----
    __shared__ int sh[8][STEPS];
    sh[w][lane] = acc;
    __syncthreads();
    if (w == 0) {
        int ssum = 0;
        #pragma unroll
        for (int ww = 0; ww < 8; ++ww) ssum += sh[ww][lane];
        if (ssum != 0) atomicAdd(&g_ecc[img * STEPS + lane], ssum);
        __threadfence();                       // order g_ecc adds before g_done

        unsigned int d = 0;
        if (lane == 0) d = atomicAdd(&g_done, 1u);
        d = __shfl_sync(0xFFFFFFFFu, d, 0);

        if (d == (unsigned)(NSTRIPS * NIMG) - 1u) {   // last block: finalize
            __threadfence();                   // acquire all blocks' g_ecc
            #pragma unroll
            for (int it = 0; it < (NIMG * STEPS) / 32; ++it) {
                const int idx = it * 32 + lane;
                int v = atomicExch(&g_ecc[idx], 0);   // read + reset for replay
                out[idx] = (float)v;
            }
            if (lane == 0) g_done = 0u;
        }
    }
}

extern "C" void kernel_launch(void* const* d_in, const int* in_sizes, int n_in,
                              void* d_out, int out_size) {
    const float* x = (const float*)d_in[0];
    float* out = (float*)d_out;
    (void)in_sizes; (void)n_in; (void)out_size;

    dim3 grid(NSTRIPS, NIMG);
    dim3 block(32, 8);
    ecc_fused_kernel<<<grid, block>>>(x, out);
}

// round 16
// speedup vs baseline: 1.0227x; 1.0227x over previous
#include <cuda_runtime.h>
#include <stdint.h>

#define HH 224
#define WW 224
#define STEPS 32
#define NIMG 24            // 8 * 3
#define RPS 3              // site rows per strip
#define NROWS (RPS + 1)    // pixel rows touched (incl. top halo)
#define NSTRIPS 76         // 76*3 = 228 >= 225 (last strip self-masks)
#define GX (NSTRIPS / 2)   // 38 blocks in x; each block = 2 strips x 2 halves
#define NBLOCKS (GX * NIMG)

// Per-image/threshold ECC accumulators + completion counter.
// Zero-initialized at load; the last block resets them each launch, so the
// "all zero at entry" invariant holds across graph replays.
__device__ int g_ecc[NIMG * STEPS];
__device__ unsigned int g_done;

// Exact cumulative indicator mask: bit j set iff v <= t_j, where
// t_j = fl(-2 + fl(j * fl(4/31))) (bit-identical to jnp.linspace(-2,2,32) f32).
// g = (v+2)*7.75 + 1/64 bias: floor(clamp(g)) is k* or k*-1; one compare
// v > t_k fixes it exactly. k==32 (v > t_31, incl. +inf) -> mask 0.
__device__ __forceinline__ unsigned int mask_of(float v) {
    float g = __fmaf_rn(v, 7.75f, 15.515625f);
    g = fminf(fmaxf(g, 0.0f), 31.0f);
    int k = (int)g;
    float t = __fadd_rn(-2.0f, __fmul_rn((float)k, 4.0f / 31.0f));
    k += (v > t) ? 1 : 0;
    return (unsigned int)(0xFFFFFFFFull << k);
}

__global__ __launch_bounds__(128, 8)
void ecc_fused_kernel(const float* __restrict__ x, float* __restrict__ out) {
    const int lane = threadIdx.x;              // 0..31
    const int w    = threadIdx.y;              // 0..3
    const int img  = blockIdx.y;               // 0..23

    // warp -> (strip, column half). Lane owns site cols c0..c0+3.
    const int strip = blockIdx.x * 2 + (w >> 1);
    const int half  = w & 1;
    const int i0    = strip * RPS;             // first site row of strip
    const int c0    = (half << 7) + 4 * lane;  // pixel col base of this lane
    const bool loadable = (c0 <= WW - 4);      // float4 fully in-bounds
    const bool haloL    = (lane == 0) && half; // needs pixel col 127

    const float* __restrict__ base = x + img * (HH * WW);

    // ---- load NROWS pixel rows (clamped, single path) + masks ----
    unsigned A0[NROWS], A1[NROWS], A2[NROWS], A3[NROWS], AL[NROWS];
    #pragma unroll
    for (int t = 0; t < NROWS; ++t) {
        const int pr  = i0 - 1 + t;                         // pixel row, may be OOB
        const int prc = min(max(pr, 0), HH - 1);            // clamped: always valid
        const unsigned rv = ((unsigned)pr < (unsigned)HH) ? 0xFFFFFFFFu : 0u;

        float4 v = make_float4(0.f, 0.f, 0.f, 0.f);
        if (loadable) v = __ldg((const float4*)(base + prc * WW + c0));
        float hv = 0.f;
        if (haloL) hv = __ldg(base + prc * WW + 127);

        const unsigned cvrv = loadable ? rv : 0u;
        A0[t] = mask_of(v.x) & cvrv;
        A1[t] = mask_of(v.y) & cvrv;
        A2[t] = mask_of(v.z) & cvrv;
        A3[t] = mask_of(v.w) & cvrv;
        AL[t] = haloL ? (mask_of(hv) & rv) : 0u;
    }

    // left-neighbor mask per row: lane L gets lane L-1's col (c0-1); lane 0 = halo
    unsigned L[NROWS];
    #pragma unroll
    for (int t = 0; t < NROWS; ++t) {
        const unsigned y = __shfl_up_sync(0xFFFFFFFFu, A3[t], 1);
        L[t] = lane ? y : AL[t];
    }

    // ---- body: RPS site rows x 4 site cols per lane ----
    // Per-thread per-bit event count <= 6 (independent-set bound on 3x4 grid),
    // so 3 bit-planes (capacity 7) are required and sufficient.
    unsigned P0 = 0u, P1 = 0u, P2 = 0u, M0 = 0u, M1 = 0u, M2 = 0u;
    #pragma unroll
    for (int r = 0; r < RPS; ++r) {
        const unsigned pl = L[r],     p0 = A0[r], p1 = A1[r], p2 = A2[r], p3 = A3[r];
        const unsigned cl = L[r + 1], q0 = A0[r + 1], q1 = A1[r + 1],
                       q2 = A2[r + 1], q3 = A3[r + 1];
        // site (a=up-left, b=up, c=left, d=own): net = a&~(b|c|d)  -  b&c&~d
        #define ECC_SITE(a, b, c, d)                                      \
            do {                                                          \
                const unsigned u_    = (b) | (c) | (d);                   \
                const unsigned plus_ = (a) & ~u_;                         \
                const unsigned min_  = (b) & (c) & ~(d);                  \
                unsigned t0_, t1_;                                        \
                t0_ = P0 & plus_; P0 ^= plus_;                            \
                t1_ = P1 & t0_;   P1 ^= t0_;   P2 ^= t1_;                 \
                t0_ = M0 & min_;  M0 ^= min_;                             \
                t1_ = M1 & t0_;   M1 ^= t0_;   M2 ^= t1_;                 \
            } while (0)
        ECC_SITE(pl, p0, cl, q0);
        ECC_SITE(p0, p1, q0, q1);
        ECC_SITE(p1, p2, q1, q2);
        ECC_SITE(p2, p3, q2, q3);
        #undef ECC_SITE
    }

    // ---- per-warp 32x32 bit transpose (3 instr/stage) + weighted popc ----
    unsigned keepm[5]; int amt[5];
    {
        const unsigned Ms[5] = {0xFFFF0000u, 0xFF00FF00u, 0xF0F0F0F0u,
                                0xCCCCCCCCu, 0xAAAAAAAAu};
        const int ds[5] = {16, 8, 4, 2, 1};
        #pragma unroll
        for (int s = 0; s < 5; ++s) {
            const bool b = (lane & ds[s]) != 0;
            keepm[s] = b ? Ms[s] : ~Ms[s];
            amt[s]   = b ? ds[s] : 32 - ds[s];
        }
    }
    int acc = 0;
    {
        const unsigned planes[6] = {P0, P1, P2, M0, M1, M2};
        const int wts[6] = {1, 2, 4, -1, -2, -4};
        #pragma unroll
        for (int k = 0; k < 6; ++k) {
            unsigned v = planes[k];
            const int ds[5] = {16, 8, 4, 2, 1};
            #pragma unroll
            for (int s = 0; s < 5; ++s) {
                const unsigned y = __shfl_xor_sync(0xFFFFFFFFu, v, ds[s]);
                const unsigned r = __funnelshift_r(y, y, amt[s]); // rotate = both arms
                v = (v & keepm[s]) | (r & ~keepm[s]);             // 1 LOP3
            }
            acc += wts[k] * __popc(v);
        }
    }
    // lane j now holds this warp's net count for threshold j.

    // ---- single barrier; warp 0 owns the whole tail ----
    __shared__ int sh[4][STEPS];
    sh[w][lane] = acc;
    __syncthreads();
    if (w == 0) {
        int ssum = sh[0][lane] + sh[1][lane] + sh[2][lane] + sh[3][lane];
        if (ssum != 0) atomicAdd(&g_ecc[img * STEPS + lane], ssum);
        __threadfence();                       // order g_ecc adds before g_done

        unsigned int d = 0;
        if (lane == 0) d = atomicAdd(&g_done, 1u);
        d = __shfl_sync(0xFFFFFFFFu, d, 0);

        if (d == (unsigned)NBLOCKS - 1u) {     // last block: finalize
            __threadfence();                   // acquire all blocks' g_ecc
            #pragma unroll
            for (int it = 0; it < (NIMG * STEPS) / 32; ++it) {
                const int idx = it * 32 + lane;
                const int v = atomicExch(&g_ecc[idx], 0);  // read + reset for replay
                out[idx] = (float)v;
            }
            if (lane == 0) g_done = 0u;
        }
    }
}

extern "C" void kernel_launch(void* const* d_in, const int* in_sizes, int n_in,
                              void* d_out, int out_size) {
    const float* x = (const float*)d_in[0];
    float* out = (float*)d_out;
    (void)in_sizes; (void)n_in; (void)out_size;

    dim3 grid(GX, NIMG);
    dim3 block(32, 4);
    ecc_fused_kernel<<<grid, block>>>(x, out);
}